// round 6
// baseline (speedup 1.0000x reference)
#include <cuda_runtime.h>
#include <math.h>

#define N_NODES 8192
#define P_META 3
#define IN_F 256
#define HIDD 64
#define N_HEADS 8
#define HD 512
#define OUT_F 64
#define NE 262144

// ---------------- scratch (static device allocations; no runtime alloc) ----
__device__ float d_feat[P_META][N_NODES * HD];    // 48 MB
__device__ float d_zp[P_META][N_NODES * HD];      // 48 MB
__device__ float d_el[P_META][N_NODES * N_HEADS];
__device__ float d_er[P_META][N_NODES * N_HEADS];
__device__ float d_invd[P_META][N_NODES * N_HEADS];
__device__ int   d_counts[P_META][N_NODES];
__device__ int   d_cursor[P_META][N_NODES];
__device__ int   d_offsets[P_META][N_NODES + 1];
__device__ int   d_csrsrc[P_META][NE];
__device__ float d_wsum[P_META];
__device__ float d_beta[P_META];
__device__ float d_v[HD];                         // W1 @ W2 collapsed
__device__ float d_c;                             // b1 . W2
__device__ float d_z[N_NODES * HD];               // beta-combined features

// ---------------------------------------------------------------- utilities
__global__ void zero_misc_kernel() {
    int p = blockIdx.y;
    int i = blockIdx.x * blockDim.x + threadIdx.x;
    if (i < N_NODES) d_counts[p][i] = 0;
    if (p == 0 && i < P_META) d_wsum[i] = 0.f;
}

__global__ void zero_atten_kernel(float4* a) {
    int i = blockIdx.x * blockDim.x + threadIdx.x;   // N*N/4 elements
    a[i] = make_float4(0.f, 0.f, 0.f, 0.f);
}

// ------------------------------------------------ feat = h @ fc_p + fused el/er
// M=8192, K=256, N=512, batched over p via blockIdx.z.
// Block (bx,by,p): rows [by*128, +128), cols [bx*128, +128) = heads 2bx, 2bx+1
// -> el/er for those heads reduce entirely within the block (shfl over 8-lane
//    groups), eliminating the separate eler kernel and a feat re-read.
__global__ void __launch_bounds__(256, 2)
gemm_feat_kernel(const float* __restrict__ A,    // [8192,256]
                 const float* __restrict__ fc,   // [P,256,512]
                 const float* __restrict__ alw,  // [P,8,64]
                 const float* __restrict__ arw) {// [P,8,64]
    const int p = blockIdx.z;
    const float* __restrict__ B = fc + (size_t)p * IN_F * HD;
    float* __restrict__ C = d_feat[p];
    __shared__ float As[8][128];
    __shared__ float Bs[8][128];
    const int bm = blockIdx.y * 128;
    const int bn = blockIdx.x * 128;
    const int t = threadIdx.x;
    const int ty = t >> 4, tx = t & 15;

    const int arow = t >> 1;
    const int acol = (t & 1) * 4;
    const int brow = t >> 5;
    const int bcol = (t & 31) * 4;

    float acc[8][8];
#pragma unroll
    for (int i = 0; i < 8; i++)
#pragma unroll
        for (int j = 0; j < 8; j++) acc[i][j] = 0.f;

    for (int k0 = 0; k0 < IN_F; k0 += 8) {
        float4 av = *(const float4*)&A[(size_t)(bm + arow) * IN_F + k0 + acol];
        float4 bv = *(const float4*)&B[(size_t)(k0 + brow) * HD + bn + bcol];
        __syncthreads();
        As[acol + 0][arow] = av.x;
        As[acol + 1][arow] = av.y;
        As[acol + 2][arow] = av.z;
        As[acol + 3][arow] = av.w;
        *(float4*)&Bs[brow][bcol] = bv;
        __syncthreads();
#pragma unroll
        for (int k = 0; k < 8; k++) {
            float a[8], b[8];
            *(float4*)&a[0] = *(const float4*)&As[k][ty * 8];
            *(float4*)&a[4] = *(const float4*)&As[k][ty * 8 + 4];
            *(float4*)&b[0] = *(const float4*)&Bs[k][tx * 8];
            *(float4*)&b[4] = *(const float4*)&Bs[k][tx * 8 + 4];
#pragma unroll
            for (int i = 0; i < 8; i++)
#pragma unroll
                for (int j = 0; j < 8; j++) acc[i][j] += a[i] * b[j];
        }
    }
#pragma unroll
    for (int i = 0; i < 8; i++) {
        float* cr = &C[(size_t)(bm + ty * 8 + i) * HD + bn + tx * 8];
        *(float4*)&cr[0] = make_float4(acc[i][0], acc[i][1], acc[i][2], acc[i][3]);
        *(float4*)&cr[4] = make_float4(acc[i][4], acc[i][5], acc[i][6], acc[i][7]);
    }

    // ---- fused el/er epilogue ----
    // thread covers cols bn+tx*8..+7 (one head half: head = 2*bx + tx/8)
    float alv[8], arv[8];
#pragma unroll
    for (int j = 0; j < 8; j++) {
        alv[j] = alw[p * HD + bn + tx * 8 + j];
        arv[j] = arw[p * HD + bn + tx * 8 + j];
    }
    float pel[8], per[8];
#pragma unroll
    for (int i = 0; i < 8; i++) {
        float sl = 0.f, sr = 0.f;
#pragma unroll
        for (int j = 0; j < 8; j++) {
            sl += acc[i][j] * alv[j];
            sr += acc[i][j] * arv[j];
        }
        pel[i] = sl;
        per[i] = sr;
    }
    // reduce across the 8 lanes sharing (row group, head): lanes differ in tx%8
#pragma unroll
    for (int o = 1; o < 8; o <<= 1) {
#pragma unroll
        for (int i = 0; i < 8; i++) {
            pel[i] += __shfl_xor_sync(0xffffffffu, pel[i], o);
            per[i] += __shfl_xor_sync(0xffffffffu, per[i], o);
        }
    }
    int lane = t & 31;
    if ((lane & 7) == 0) {
        int head = blockIdx.x * 2 + ((tx >> 3) & 1);
#pragma unroll
        for (int i = 0; i < 8; i++) {
            int row = bm + ty * 8 + i;
            d_el[p][row * N_HEADS + head] = pel[i];
            d_er[p][row * N_HEADS + head] = per[i];
        }
    }
}

// ------------------------------------------------ CSR build by dst
__global__ void hist_kernel(const int* __restrict__ dst) {
    int p = blockIdx.y;
    int e = blockIdx.x * blockDim.x + threadIdx.x;
    if (e < NE) atomicAdd(&d_counts[p][dst[p * NE + e]], 1);
}

__global__ void scan_kernel() {
    int p = blockIdx.x;
    __shared__ int sh[1024];
    int t = threadIdx.x;
    int base = t * 8;
    int loc[8];
    int s = 0;
#pragma unroll
    for (int i = 0; i < 8; i++) { loc[i] = s; s += d_counts[p][base + i]; }
    sh[t] = s;
    __syncthreads();
    for (int ofs = 1; ofs < 1024; ofs <<= 1) {
        int v = (t >= ofs) ? sh[t - ofs] : 0;
        __syncthreads();
        sh[t] += v;
        __syncthreads();
    }
    int pre = (t == 0) ? 0 : sh[t - 1];
#pragma unroll
    for (int i = 0; i < 8; i++) {
        int o = pre + loc[i];
        d_offsets[p][base + i] = o;
        d_cursor[p][base + i] = o;
    }
    if (t == 1023) d_offsets[p][N_NODES] = sh[1023];
}

__global__ void csr_scatter_kernel(const int* __restrict__ src,
                                   const int* __restrict__ dst) {
    int p = blockIdx.y;
    int e = blockIdx.x * blockDim.x + threadIdx.x;
    if (e < NE) {
        int pos = atomicAdd(&d_cursor[p][dst[p * NE + e]], 1);
        d_csrsrc[p][pos] = src[p * NE + e];
    }
}

// ------------------------------------------------ single-pass softmax + aggregation
// one warp per (dst, head); accumulate unnormalized Σexp·feat and Σexp in ONE
// sweep, normalize at the end. Depth-1 software pipeline hides gather latency.
__global__ void gat_aggregate_kernel(const float* __restrict__ bias) {
    int p = blockIdx.y;
    int dn = blockIdx.x;
    int h = threadIdx.x >> 5;
    int lane = threadIdx.x & 31;
    int s0 = d_offsets[p][dn], s1 = d_offsets[p][dn + 1];
    float erv = d_er[p][dn * N_HEADS + h];
    const float* __restrict__ el = d_el[p];
    const int* __restrict__ csrc = d_csrsrc[p];
    const float* fb = &d_feat[p][h * HIDD + lane * 2];

    float ssum = 0.f, accx = 0.f, accy = 0.f;
    int i = s0;
    int s = 0; float elv = 0.f; float2 f = make_float2(0.f, 0.f);
    if (i < s1) {
        s = csrc[i];
        elv = el[s * N_HEADS + h];
        f = *(const float2*)(fb + (size_t)s * HD);
    }
    while (i < s1) {
        int s2 = 0; float elv2 = 0.f; float2 f2 = make_float2(0.f, 0.f);
        if (i + 1 < s1) {
            s2 = csrc[i + 1];
            elv2 = el[s2 * N_HEADS + h];
            f2 = *(const float2*)(fb + (size_t)s2 * HD);
        }
        float ev = elv + erv;
        ev = ev > 0.f ? ev : 0.2f * ev;
        float a = __expf(ev);
        ssum += a;
        accx += a * f.x;
        accy += a * f.y;
        s = s2; elv = elv2; f = f2;
        i++;
    }
    float inv = ssum > 0.f ? 1.f / ssum : 0.f;
    if (lane == 0) d_invd[p][dn * N_HEADS + h] = inv;

    float bx = bias[p * HD + h * HIDD + lane * 2];
    float by = bias[p * HD + h * HIDD + lane * 2 + 1];
    float ox = accx * inv + bx, oy = accy * inv + by;
    ox = ox > 0.f ? ox : (__expf(ox) - 1.f);   // elu
    oy = oy > 0.f ? oy : (__expf(oy) - 1.f);
    *(float2*)&d_zp[p][(size_t)dn * HD + h * HIDD + lane * 2] = make_float2(ox, oy);
}

// ------------------------------------------------ semantic attention
__global__ void sem_v_kernel(const float* __restrict__ w1,
                             const float* __restrict__ w2,
                             const float* __restrict__ b1) {
    int k = threadIdx.x + blockIdx.x * blockDim.x;   // 512
    float s = 0.f;
    for (int j = 0; j < 128; j++) s += w1[k * 128 + j] * w2[j];
    d_v[k] = s;
    if (k == 0) {
        float c = 0.f;
        for (int j = 0; j < 128; j++) c += b1[j] * w2[j];
        d_c = c;
    }
}

__global__ void sem_w_kernel() {
    int gw = (blockIdx.x * blockDim.x + threadIdx.x) >> 5;   // N*P warps
    int lane = threadIdx.x & 31;
    int n = gw / P_META;
    int p = gw - n * P_META;
    if (n >= N_NODES) return;
    const float* z = &d_zp[p][(size_t)n * HD];
    float s = 0.f;
#pragma unroll
    for (int k = lane; k < HD; k += 32) s += z[k] * d_v[k];
#pragma unroll
    for (int o = 16; o; o >>= 1) s += __shfl_xor_sync(0xffffffffu, s, o);
    if (lane == 0) {
        float w = s + d_c;
        w = w > 0.f ? w : 0.01f * w;
        atomicAdd(&d_wsum[p], w);
    }
}

__global__ void beta_kernel() {
    if (threadIdx.x == 0) {
        float w0 = d_wsum[0] / (float)N_NODES;
        float w1 = d_wsum[1] / (float)N_NODES;
        float w2 = d_wsum[2] / (float)N_NODES;
        float mx = fmaxf(w0, fmaxf(w1, w2));
        float e0 = expf(w0 - mx), e1 = expf(w1 - mx), e2 = expf(w2 - mx);
        float s = e0 + e1 + e2;
        d_beta[0] = e0 / s;
        d_beta[1] = e1 / s;
        d_beta[2] = e2 / s;
    }
}

// ------------------------------------------------ z = sum_p beta_p * zp
__global__ void combine_z_kernel() {
    int i = blockIdx.x * blockDim.x + threadIdx.x;   // N*HD/4
    float b0 = d_beta[0], b1 = d_beta[1], b2 = d_beta[2];
    float4 a = ((const float4*)&d_zp[0][0])[i];
    float4 b = ((const float4*)&d_zp[1][0])[i];
    float4 c = ((const float4*)&d_zp[2][0])[i];
    float4 r;
    r.x = b0 * a.x + b1 * b.x + b2 * c.x;
    r.y = b0 * a.y + b1 * b.y + b2 * c.y;
    r.z = b0 * a.z + b1 * b.z + b2 * c.z;
    r.w = b0 * a.w + b1 * b.w + b2 * c.w;
    ((float4*)d_z)[i] = r;
}

// ------------------------------------------------ out = z @ pred_w + pred_b
__global__ void out_kernel(const float* __restrict__ pw,
                           const float* __restrict__ pb,
                           float* __restrict__ out) {
    __shared__ float zs[HD];
    int n = blockIdx.x;
    int t = threadIdx.x;   // 64
    for (int k = t; k < HD; k += 64) zs[k] = d_z[(size_t)n * HD + k];
    __syncthreads();
    float acc = pb[t];
#pragma unroll 8
    for (int k = 0; k < HD; k++) acc += zs[k] * pw[k * OUT_F + t];
    out[(size_t)n * OUT_F + t] = acc;
}

// ------------------------------------------------ atten scatter (fused alpha)
__global__ void atten_scatter_kernel(const int* __restrict__ src,
                                     const int* __restrict__ dst,
                                     float* __restrict__ atten) {
    int p = blockIdx.y;
    int e = blockIdx.x * blockDim.x + threadIdx.x;
    if (e >= NE) return;
    int s = src[p * NE + e];
    int d = dst[p * NE + e];
    const float* elrow = &d_el[p][s * N_HEADS];
    const float* errow = &d_er[p][d * N_HEADS];
    const float* invrow = &d_invd[p][d * N_HEADS];
    float a = 0.f;
#pragma unroll
    for (int h = 0; h < N_HEADS; h++) {
        float ev = elrow[h] + errow[h];
        ev = ev > 0.f ? ev : 0.2f * ev;
        a += __expf(ev) * invrow[h];
    }
    float v = a * 0.125f * d_beta[p];
    atomicAdd(&atten[(size_t)s * N_NODES + d], v);
}

// ---------------------------------------------------------------- launcher
extern "C" void kernel_launch(void* const* d_in, const int* in_sizes, int n_in,
                              void* d_out, int out_size) {
    const float* h    = (const float*)d_in[0];
    const int*   esrc = (const int*)d_in[1];
    const int*   edst = (const int*)d_in[2];
    const float* fc   = (const float*)d_in[3];
    const float* al   = (const float*)d_in[4];
    const float* ar   = (const float*)d_in[5];
    const float* bias = (const float*)d_in[6];
    const float* w1   = (const float*)d_in[7];
    const float* b1   = (const float*)d_in[8];
    const float* w2   = (const float*)d_in[9];
    const float* pw   = (const float*)d_in[10];
    const float* pb   = (const float*)d_in[11];

    const long long SZ_OUT   = (long long)N_NODES * OUT_F;      // 524288
    const long long SZ_ATTEN = (long long)N_NODES * N_NODES;    // 67108864
    long long osz = (long long)out_size;

    float* out_ptr = nullptr;
    float* atten_ptr = nullptr;
    if (osz >= SZ_OUT + SZ_ATTEN) {
        out_ptr = (float*)d_out;                 // [out | atten]
        atten_ptr = out_ptr + SZ_OUT;
    } else if (osz == SZ_OUT) {
        out_ptr = (float*)d_out;
    } else if (osz == SZ_ATTEN) {
        atten_ptr = (float*)d_out;
    } else {
        out_ptr = (float*)d_out;
    }

    zero_misc_kernel<<<dim3(N_NODES / 256, P_META), 256>>>();
    if (atten_ptr)
        zero_atten_kernel<<<(N_NODES * (N_NODES / 4)) / 256, 256>>>((float4*)atten_ptr);

    // CSR build is independent of the GEMM — issue first for better overlap
    hist_kernel<<<dim3(NE / 256, P_META), 256>>>(edst);
    scan_kernel<<<P_META, 1024>>>();
    csr_scatter_kernel<<<dim3(NE / 256, P_META), 256>>>(esrc, edst);

    gemm_feat_kernel<<<dim3(HD / 128, N_NODES / 128, P_META), 256>>>(h, fc, al, ar);
    gat_aggregate_kernel<<<dim3(N_NODES, P_META), 256>>>(bias);

    sem_v_kernel<<<2, 256>>>(w1, w2, b1);
    sem_w_kernel<<<(N_NODES * P_META * 32) / 256, 256>>>();
    beta_kernel<<<1, 32>>>();
    combine_z_kernel<<<(N_NODES * HD / 4) / 256, 256>>>();
    if (out_ptr)
        out_kernel<<<N_NODES, 64>>>(pw, pb, out_ptr);
    if (atten_ptr)
        atten_scatter_kernel<<<dim3(NE / 256, P_META), 256>>>(esrc, edst, atten_ptr);
}

// round 7
// speedup vs baseline: 1.0337x; 1.0337x over previous
#include <cuda_runtime.h>
#include <math.h>

#define N_NODES 8192
#define P_META 3
#define IN_F 256
#define HIDD 64
#define N_HEADS 8
#define HD 512
#define OUT_F 64
#define NE 262144

// ---------------- scratch (static device allocations; no runtime alloc) ----
__device__ float d_feat[P_META][N_NODES * HD];    // 48 MB
__device__ float d_zp[P_META][N_NODES * HD];      // 48 MB
__device__ float d_el[P_META][N_NODES * N_HEADS];
__device__ float d_er[P_META][N_NODES * N_HEADS];
__device__ float d_invd[P_META][N_NODES * N_HEADS];
__device__ int   d_counts[P_META][N_NODES];
__device__ int   d_cursor[P_META][N_NODES];
__device__ int   d_offsets[P_META][N_NODES + 1];
__device__ int   d_csrsrc[P_META][NE];
__device__ float d_wsum[P_META];
__device__ float d_beta[P_META];
__device__ float d_v[HD];                         // W1 @ W2 collapsed
__device__ float d_c;                             // b1 . W2
__device__ float d_z[N_NODES * HD];               // beta-combined features

// ---------------------------------------------------------------- utilities
__global__ void zero_misc_kernel() {
    int p = blockIdx.y;
    int i = blockIdx.x * blockDim.x + threadIdx.x;
    if (i < N_NODES) d_counts[p][i] = 0;
    if (p == 0 && i < P_META) d_wsum[i] = 0.f;
}

__global__ void zero_atten_kernel(float4* a) {
    int i = blockIdx.x * blockDim.x + threadIdx.x;   // N*N/4 elements
    a[i] = make_float4(0.f, 0.f, 0.f, 0.f);
}

// ------------------------------------------------ feat = h @ fc_p (fp32 GEMM)
// M=8192, K=256, N=512, batched over p. Clean 127-reg version (NO epilogue —
// the fused el/er variant spilled past the 128-reg cap and regressed).
__global__ void __launch_bounds__(256, 2)
gemm_feat_kernel(const float* __restrict__ A,    // [8192,256]
                 const float* __restrict__ fc) { // [P,256,512]
    const int p = blockIdx.z;
    const float* __restrict__ B = fc + (size_t)p * IN_F * HD;
    float* __restrict__ C = d_feat[p];
    __shared__ float As[8][128];
    __shared__ float Bs[8][128];
    const int bm = blockIdx.y * 128;
    const int bn = blockIdx.x * 128;
    const int t = threadIdx.x;
    const int ty = t >> 4, tx = t & 15;

    const int arow = t >> 1;
    const int acol = (t & 1) * 4;
    const int brow = t >> 5;
    const int bcol = (t & 31) * 4;

    float acc[8][8];
#pragma unroll
    for (int i = 0; i < 8; i++)
#pragma unroll
        for (int j = 0; j < 8; j++) acc[i][j] = 0.f;

    for (int k0 = 0; k0 < IN_F; k0 += 8) {
        float4 av = *(const float4*)&A[(size_t)(bm + arow) * IN_F + k0 + acol];
        float4 bv = *(const float4*)&B[(size_t)(k0 + brow) * HD + bn + bcol];
        __syncthreads();
        As[acol + 0][arow] = av.x;
        As[acol + 1][arow] = av.y;
        As[acol + 2][arow] = av.z;
        As[acol + 3][arow] = av.w;
        *(float4*)&Bs[brow][bcol] = bv;
        __syncthreads();
#pragma unroll
        for (int k = 0; k < 8; k++) {
            float a[8], b[8];
            *(float4*)&a[0] = *(const float4*)&As[k][ty * 8];
            *(float4*)&a[4] = *(const float4*)&As[k][ty * 8 + 4];
            *(float4*)&b[0] = *(const float4*)&Bs[k][tx * 8];
            *(float4*)&b[4] = *(const float4*)&Bs[k][tx * 8 + 4];
#pragma unroll
            for (int i = 0; i < 8; i++)
#pragma unroll
                for (int j = 0; j < 8; j++) acc[i][j] += a[i] * b[j];
        }
    }
#pragma unroll
    for (int i = 0; i < 8; i++) {
        float* cr = &C[(size_t)(bm + ty * 8 + i) * HD + bn + tx * 8];
        *(float4*)&cr[0] = make_float4(acc[i][0], acc[i][1], acc[i][2], acc[i][3]);
        *(float4*)&cr[4] = make_float4(acc[i][4], acc[i][5], acc[i][6], acc[i][7]);
    }
}

// ------------------------------------------------ el/er per (node, head, p)
__global__ void eler_kernel(const float* __restrict__ al,
                            const float* __restrict__ ar) {
    int p = blockIdx.y;
    int n = blockIdx.x;
    int h = threadIdx.x >> 5;
    int lane = threadIdx.x & 31;
    float2 f = *(const float2*)&d_feat[p][(size_t)n * HD + h * HIDD + lane * 2];
    float2 a = *(const float2*)&al[p * HD + h * HIDD + lane * 2];
    float2 b = *(const float2*)&ar[p * HD + h * HIDD + lane * 2];
    float sl = f.x * a.x + f.y * a.y;
    float sr = f.x * b.x + f.y * b.y;
#pragma unroll
    for (int o = 16; o; o >>= 1) {
        sl += __shfl_xor_sync(0xffffffffu, sl, o);
        sr += __shfl_xor_sync(0xffffffffu, sr, o);
    }
    if (lane == 0) {
        d_el[p][n * N_HEADS + h] = sl;
        d_er[p][n * N_HEADS + h] = sr;
    }
}

// ------------------------------------------------ CSR build by dst
__global__ void hist_kernel(const int* __restrict__ dst) {
    int p = blockIdx.y;
    int e = blockIdx.x * blockDim.x + threadIdx.x;
    if (e < NE) atomicAdd(&d_counts[p][dst[p * NE + e]], 1);
}

__global__ void scan_kernel() {
    int p = blockIdx.x;
    __shared__ int sh[1024];
    int t = threadIdx.x;
    int base = t * 8;
    int loc[8];
    int s = 0;
#pragma unroll
    for (int i = 0; i < 8; i++) { loc[i] = s; s += d_counts[p][base + i]; }
    sh[t] = s;
    __syncthreads();
    for (int ofs = 1; ofs < 1024; ofs <<= 1) {
        int v = (t >= ofs) ? sh[t - ofs] : 0;
        __syncthreads();
        sh[t] += v;
        __syncthreads();
    }
    int pre = (t == 0) ? 0 : sh[t - 1];
#pragma unroll
    for (int i = 0; i < 8; i++) {
        int o = pre + loc[i];
        d_offsets[p][base + i] = o;
        d_cursor[p][base + i] = o;
    }
    if (t == 1023) d_offsets[p][N_NODES] = sh[1023];
}

__global__ void csr_scatter_kernel(const int* __restrict__ src,
                                   const int* __restrict__ dst) {
    int p = blockIdx.y;
    int e = blockIdx.x * blockDim.x + threadIdx.x;
    if (e < NE) {
        int pos = atomicAdd(&d_cursor[p][dst[p * NE + e]], 1);
        d_csrsrc[p][pos] = src[p * NE + e];
    }
}

// ------------------------------------------------ single-pass softmax + aggregation
// one warp per (dst, head). Unnormalized Σexp·feat + Σexp in one sweep,
// unrolled x4 with batched prefetch (MLP≈4-8) to hide the L2 gather latency.
__global__ void gat_aggregate_kernel(const float* __restrict__ bias) {
    int p = blockIdx.y;
    int dn = blockIdx.x;
    int h = threadIdx.x >> 5;
    int lane = threadIdx.x & 31;
    int s0 = d_offsets[p][dn], s1 = d_offsets[p][dn + 1];
    float erv = d_er[p][dn * N_HEADS + h];
    const float* __restrict__ el = d_el[p];
    const int* __restrict__ csrc = d_csrsrc[p];
    const float* fb = &d_feat[p][h * HIDD + lane * 2];

    float ssum = 0.f, accx = 0.f, accy = 0.f;

    int i = s0;
    // unrolled-by-4 main body with batched loads
    for (; i + 4 <= s1; i += 4) {
        int s_0 = csrc[i + 0];
        int s_1 = csrc[i + 1];
        int s_2 = csrc[i + 2];
        int s_3 = csrc[i + 3];
        float e_0 = el[s_0 * N_HEADS + h];
        float e_1 = el[s_1 * N_HEADS + h];
        float e_2 = el[s_2 * N_HEADS + h];
        float e_3 = el[s_3 * N_HEADS + h];
        float2 f_0 = *(const float2*)(fb + (size_t)s_0 * HD);
        float2 f_1 = *(const float2*)(fb + (size_t)s_1 * HD);
        float2 f_2 = *(const float2*)(fb + (size_t)s_2 * HD);
        float2 f_3 = *(const float2*)(fb + (size_t)s_3 * HD);

        float v0 = e_0 + erv; v0 = v0 > 0.f ? v0 : 0.2f * v0;
        float v1 = e_1 + erv; v1 = v1 > 0.f ? v1 : 0.2f * v1;
        float v2 = e_2 + erv; v2 = v2 > 0.f ? v2 : 0.2f * v2;
        float v3 = e_3 + erv; v3 = v3 > 0.f ? v3 : 0.2f * v3;
        float a0 = __expf(v0), a1 = __expf(v1), a2 = __expf(v2), a3 = __expf(v3);
        ssum += (a0 + a1) + (a2 + a3);
        accx += a0 * f_0.x + a1 * f_1.x + a2 * f_2.x + a3 * f_3.x;
        accy += a0 * f_0.y + a1 * f_1.y + a2 * f_2.y + a3 * f_3.y;
    }
    // remainder
    for (; i < s1; i++) {
        int s = csrc[i];
        float ev = el[s * N_HEADS + h] + erv;
        ev = ev > 0.f ? ev : 0.2f * ev;
        float a = __expf(ev);
        float2 f = *(const float2*)(fb + (size_t)s * HD);
        ssum += a;
        accx += a * f.x;
        accy += a * f.y;
    }

    float inv = ssum > 0.f ? 1.f / ssum : 0.f;
    if (lane == 0) d_invd[p][dn * N_HEADS + h] = inv;

    float bx = bias[p * HD + h * HIDD + lane * 2];
    float by = bias[p * HD + h * HIDD + lane * 2 + 1];
    float ox = accx * inv + bx, oy = accy * inv + by;
    ox = ox > 0.f ? ox : (__expf(ox) - 1.f);   // elu
    oy = oy > 0.f ? oy : (__expf(oy) - 1.f);
    *(float2*)&d_zp[p][(size_t)dn * HD + h * HIDD + lane * 2] = make_float2(ox, oy);
}

// ------------------------------------------------ semantic attention
__global__ void sem_v_kernel(const float* __restrict__ w1,
                             const float* __restrict__ w2,
                             const float* __restrict__ b1) {
    int k = threadIdx.x + blockIdx.x * blockDim.x;   // 512
    float s = 0.f;
    for (int j = 0; j < 128; j++) s += w1[k * 128 + j] * w2[j];
    d_v[k] = s;
    if (k == 0) {
        float c = 0.f;
        for (int j = 0; j < 128; j++) c += b1[j] * w2[j];
        d_c = c;
    }
}

__global__ void sem_w_kernel() {
    int gw = (blockIdx.x * blockDim.x + threadIdx.x) >> 5;   // N*P warps
    int lane = threadIdx.x & 31;
    int n = gw / P_META;
    int p = gw - n * P_META;
    if (n >= N_NODES) return;
    const float* z = &d_zp[p][(size_t)n * HD];
    float s = 0.f;
#pragma unroll
    for (int k = lane; k < HD; k += 32) s += z[k] * d_v[k];
#pragma unroll
    for (int o = 16; o; o >>= 1) s += __shfl_xor_sync(0xffffffffu, s, o);
    if (lane == 0) {
        float w = s + d_c;
        w = w > 0.f ? w : 0.01f * w;
        atomicAdd(&d_wsum[p], w);
    }
}

__global__ void beta_kernel() {
    if (threadIdx.x == 0) {
        float w0 = d_wsum[0] / (float)N_NODES;
        float w1 = d_wsum[1] / (float)N_NODES;
        float w2 = d_wsum[2] / (float)N_NODES;
        float mx = fmaxf(w0, fmaxf(w1, w2));
        float e0 = expf(w0 - mx), e1 = expf(w1 - mx), e2 = expf(w2 - mx);
        float s = e0 + e1 + e2;
        d_beta[0] = e0 / s;
        d_beta[1] = e1 / s;
        d_beta[2] = e2 / s;
    }
}

// ------------------------------------------------ z = sum_p beta_p * zp
__global__ void combine_z_kernel() {
    int i = blockIdx.x * blockDim.x + threadIdx.x;   // N*HD/4
    float b0 = d_beta[0], b1 = d_beta[1], b2 = d_beta[2];
    float4 a = ((const float4*)&d_zp[0][0])[i];
    float4 b = ((const float4*)&d_zp[1][0])[i];
    float4 c = ((const float4*)&d_zp[2][0])[i];
    float4 r;
    r.x = b0 * a.x + b1 * b.x + b2 * c.x;
    r.y = b0 * a.y + b1 * b.y + b2 * c.y;
    r.z = b0 * a.z + b1 * b.z + b2 * c.z;
    r.w = b0 * a.w + b1 * b.w + b2 * c.w;
    ((float4*)d_z)[i] = r;
}

// ------------------------------------------------ out = z @ pred_w + pred_b
__global__ void out_kernel(const float* __restrict__ pw,
                           const float* __restrict__ pb,
                           float* __restrict__ out) {
    __shared__ float zs[HD];
    int n = blockIdx.x;
    int t = threadIdx.x;   // 64
    for (int k = t; k < HD; k += 64) zs[k] = d_z[(size_t)n * HD + k];
    __syncthreads();
    float acc = pb[t];
#pragma unroll 8
    for (int k = 0; k < HD; k++) acc += zs[k] * pw[k * OUT_F + t];
    out[(size_t)n * OUT_F + t] = acc;
}

// ------------------------------------------------ atten scatter (fused alpha)
__global__ void atten_scatter_kernel(const int* __restrict__ src,
                                     const int* __restrict__ dst,
                                     float* __restrict__ atten) {
    int p = blockIdx.y;
    int e = blockIdx.x * blockDim.x + threadIdx.x;
    if (e >= NE) return;
    int s = src[p * NE + e];
    int d = dst[p * NE + e];
    const float* elrow = &d_el[p][s * N_HEADS];
    const float* errow = &d_er[p][d * N_HEADS];
    const float* invrow = &d_invd[p][d * N_HEADS];
    float a = 0.f;
#pragma unroll
    for (int h = 0; h < N_HEADS; h++) {
        float ev = elrow[h] + errow[h];
        ev = ev > 0.f ? ev : 0.2f * ev;
        a += __expf(ev) * invrow[h];
    }
    float v = a * 0.125f * d_beta[p];
    atomicAdd(&atten[(size_t)s * N_NODES + d], v);
}

// ---------------------------------------------------------------- launcher
extern "C" void kernel_launch(void* const* d_in, const int* in_sizes, int n_in,
                              void* d_out, int out_size) {
    const float* h    = (const float*)d_in[0];
    const int*   esrc = (const int*)d_in[1];
    const int*   edst = (const int*)d_in[2];
    const float* fc   = (const float*)d_in[3];
    const float* al   = (const float*)d_in[4];
    const float* ar   = (const float*)d_in[5];
    const float* bias = (const float*)d_in[6];
    const float* w1   = (const float*)d_in[7];
    const float* b1   = (const float*)d_in[8];
    const float* w2   = (const float*)d_in[9];
    const float* pw   = (const float*)d_in[10];
    const float* pb   = (const float*)d_in[11];

    const long long SZ_OUT   = (long long)N_NODES * OUT_F;      // 524288
    const long long SZ_ATTEN = (long long)N_NODES * N_NODES;    // 67108864
    long long osz = (long long)out_size;

    float* out_ptr = nullptr;
    float* atten_ptr = nullptr;
    if (osz >= SZ_OUT + SZ_ATTEN) {
        out_ptr = (float*)d_out;                 // [out | atten]
        atten_ptr = out_ptr + SZ_OUT;
    } else if (osz == SZ_OUT) {
        out_ptr = (float*)d_out;
    } else if (osz == SZ_ATTEN) {
        atten_ptr = (float*)d_out;
    } else {
        out_ptr = (float*)d_out;
    }

    zero_misc_kernel<<<dim3(N_NODES / 256, P_META), 256>>>();
    if (atten_ptr)
        zero_atten_kernel<<<(N_NODES * (N_NODES / 4)) / 256, 256>>>((float4*)atten_ptr);

    // CSR build first (independent of GEMM output)
    hist_kernel<<<dim3(NE / 256, P_META), 256>>>(edst);
    scan_kernel<<<P_META, 1024>>>();
    csr_scatter_kernel<<<dim3(NE / 256, P_META), 256>>>(esrc, edst);

    gemm_feat_kernel<<<dim3(HD / 128, N_NODES / 128, P_META), 256>>>(h, fc);
    eler_kernel<<<dim3(N_NODES, P_META), 256>>>(al, ar);
    gat_aggregate_kernel<<<dim3(N_NODES, P_META), 256>>>(bias);

    sem_v_kernel<<<2, 256>>>(w1, w2, b1);
    sem_w_kernel<<<(N_NODES * P_META * 32) / 256, 256>>>();
    beta_kernel<<<1, 32>>>();
    combine_z_kernel<<<(N_NODES * HD / 4) / 256, 256>>>();
    if (out_ptr)
        out_kernel<<<N_NODES, 64>>>(pw, pb, out_ptr);
    if (atten_ptr)
        atten_scatter_kernel<<<dim3(NE / 256, P_META), 256>>>(esrc, edst, atten_ptr);
}